// round 1
// baseline (speedup 1.0000x reference)
#include <cuda_runtime.h>
#include <math.h>

// Problem constants
#define T_SEQ 4096
#define HID   1024
#define G4    4096   // 4*HID
#define KDIM  1024   // E == H

// ---------------- device scratch (static, no allocations) ----------------
__device__ float g_pre[2][T_SEQ][G4];        // input projections, per branch (128 MB)
__device__ float g_hseq[2][T_SEQ][HID];      // per-layer hidden sequence (32 MB)
__device__ __align__(16) float2 g_hbuf[2][HID];  // double-buffered packed (h1,h2)
__device__ unsigned g_bar_count = 0;
__device__ volatile unsigned g_bar_gen = 0;

// ---------------- grid barrier (all CTAs co-resident) ----------------
#define REC_NC 128

__device__ __forceinline__ void grid_bar() {
    __syncthreads();
    if (threadIdx.x == 0) {
        unsigned gen = g_bar_gen;
        __threadfence();
        unsigned prev = atomicAdd(&g_bar_count, 1u);
        if (prev == (unsigned)REC_NC - 1u) {
            atomicExch(&g_bar_count, 0u);
            __threadfence();
            g_bar_gen = gen + 1u;
        } else {
            while (g_bar_gen == gen) { }
            __threadfence();
        }
    }
    __syncthreads();
}

// ---------------- SGEMM: pre[b][t][r] = sum_k A_b[t][k]*W[r][k] + (bi[r]+bh[r]) ----
// A row-major [4096][1024] (K contiguous), W row-major [4096][1024].
#define BM 128
#define BN 128
#define BK 8

__global__ void __launch_bounds__(256, 2)
sgemm_nt_bias(const float* __restrict__ A0, const float* __restrict__ A1,
              int from_hseq,
              const float* __restrict__ W,
              const float* __restrict__ bi, const float* __restrict__ bh)
{
    __shared__ float As[BK][BM];
    __shared__ float Bs[BK][BN];

    const int z = blockIdx.z;   // branch
    const float* A = from_hseq ? &g_hseq[z][0][0] : (z ? A1 : A0);
    float* C = &g_pre[z][0][0];

    const int m0 = blockIdx.y * BM;
    const int n0 = blockIdx.x * BN;
    const int tid = threadIdx.x;

    const int lr = tid >> 1;          // 0..127 row within tile
    const int lc = (tid & 1) * 4;     // 0 or 4 within k-tile

    float acc[8][8];
    #pragma unroll
    for (int i = 0; i < 8; ++i)
        #pragma unroll
        for (int j = 0; j < 8; ++j) acc[i][j] = 0.f;

    const int tx = tid & 15, ty = tid >> 4;

    for (int k0 = 0; k0 < KDIM; k0 += BK) {
        float4 av = *(const float4*)&A[(size_t)(m0 + lr) * KDIM + k0 + lc];
        float4 bv = *(const float4*)&W[(size_t)(n0 + lr) * KDIM + k0 + lc];
        __syncthreads();
        As[lc + 0][lr] = av.x; As[lc + 1][lr] = av.y;
        As[lc + 2][lr] = av.z; As[lc + 3][lr] = av.w;
        Bs[lc + 0][lr] = bv.x; Bs[lc + 1][lr] = bv.y;
        Bs[lc + 2][lr] = bv.z; Bs[lc + 3][lr] = bv.w;
        __syncthreads();
        #pragma unroll
        for (int kk = 0; kk < BK; ++kk) {
            float4 a0 = *(const float4*)&As[kk][ty * 8];
            float4 a1 = *(const float4*)&As[kk][ty * 8 + 4];
            float4 b0 = *(const float4*)&Bs[kk][tx * 8];
            float4 b1 = *(const float4*)&Bs[kk][tx * 8 + 4];
            float a[8] = {a0.x,a0.y,a0.z,a0.w,a1.x,a1.y,a1.z,a1.w};
            float b[8] = {b0.x,b0.y,b0.z,b0.w,b1.x,b1.y,b1.z,b1.w};
            #pragma unroll
            for (int i = 0; i < 8; ++i)
                #pragma unroll
                for (int j = 0; j < 8; ++j)
                    acc[i][j] = fmaf(a[i], b[j], acc[i][j]);
        }
    }

    // epilogue: bias add + store
    float bsum[8];
    #pragma unroll
    for (int j = 0; j < 8; ++j) {
        int n = n0 + tx * 8 + j;
        bsum[j] = bi[n] + bh[n];
    }
    #pragma unroll
    for (int i = 0; i < 8; ++i) {
        int m = m0 + ty * 8 + i;
        float* crow = C + (size_t)m * G4 + n0 + tx * 8;
        float4 v0, v1;
        v0.x = acc[i][0] + bsum[0]; v0.y = acc[i][1] + bsum[1];
        v0.z = acc[i][2] + bsum[2]; v0.w = acc[i][3] + bsum[3];
        v1.x = acc[i][4] + bsum[4]; v1.y = acc[i][5] + bsum[5];
        v1.z = acc[i][6] + bsum[6]; v1.w = acc[i][7] + bsum[7];
        *(float4*)&crow[0] = v0;
        *(float4*)&crow[4] = v1;
    }
}

// ---------------- recurrent kernel: one layer, both branches ----------------
// 128 CTAs x 256 threads. CTA c owns 8 hidden units u0=8c..8c+7, all 4 gates
// (32 rows of W_hh in SMEM). Threads: row = tid>>3 (0..31), e = tid&7 handles
// k = j*32 + e*4 (j=0..31), so SMEM weight reads spread across banks.
#define REC_SMEM (32 * 1024 * 4 + 1024 * 8 + 64 * 4)

__device__ __forceinline__ float sigm(float x) { return 1.f / (1.f + expf(-x)); }

__global__ void __launch_bounds__(256, 1)
lstm_rec(const float* __restrict__ Whh,     // [4096][1024] this layer
         const float* __restrict__ h0b0, const float* __restrict__ h0b1,
         const float* __restrict__ c0b0, const float* __restrict__ c0b1)
{
    extern __shared__ float smem[];
    float*  sW = smem;                          // 32*1024 floats
    float2* hs = (float2*)(smem + 32 * 1024);   // 1024 float2
    float*  sg = smem + 32 * 1024 + 2 * 1024;   // [2][32]

    const int tid = threadIdx.x;
    const int cta = blockIdx.x;
    const int u0  = cta * 8;

    // load W_hh rows (q,u): global row q*1024 + u0 + u -> smem row q*8+u
    #pragma unroll 1
    for (int r = 0; r < 32; ++r) {
        int q = r >> 3, u = r & 7;
        const float4* src = (const float4*)(Whh + ((size_t)(q * HID + u0 + u)) * HID);
        float4* dst = (float4*)(sW + r * HID);
        dst[tid] = src[tid];   // 256 float4 = 1024 floats
    }

    // init c (one value per (branch,unit) thread) and h buffer 0
    float c_reg = 0.f;
    if (tid < 16) {
        int b = tid >> 3, u = tid & 7;
        c_reg = (b ? c0b1 : c0b0)[u0 + u];
        float hv = (b ? h0b1 : h0b0)[u0 + u];
        ((float*)&g_hbuf[0][u0 + u])[b] = hv;
        __threadfence();
    }
    grid_bar();

    const int row = tid >> 3;
    const int e   = tid & 7;
    const float4* w4 = (const float4*)(sW + row * HID);
    const int grow = (row >> 3) * HID + u0 + (row & 7);  // global gate row

    for (int t = 0; t < T_SEQ; ++t) {
        int p = t & 1;
        // prefetch precomputed input gates for this row
        float pA = 0.f, pB = 0.f;
        if (e == 0) {
            pA = g_pre[0][t][grow];
            pB = g_pre[1][t][grow];
        }
        // broadcast h into SMEM (512 float4)
        {
            const float4* src = (const float4*)g_hbuf[p];
            float4* dst = (float4*)hs;
            dst[tid]       = src[tid];
            dst[tid + 256] = src[tid + 256];
        }
        __syncthreads();

        float a1 = 0.f, a2 = 0.f;
        const float4* h4 = (const float4*)hs;
        #pragma unroll
        for (int j = 0; j < 32; ++j) {
            float4 w  = w4[j * 8 + e];
            float4 hA = h4[j * 16 + e * 2];
            float4 hB = h4[j * 16 + e * 2 + 1];
            a1 = fmaf(w.x, hA.x, a1); a2 = fmaf(w.x, hA.y, a2);
            a1 = fmaf(w.y, hA.z, a1); a2 = fmaf(w.y, hA.w, a2);
            a1 = fmaf(w.z, hB.x, a1); a2 = fmaf(w.z, hB.y, a2);
            a1 = fmaf(w.w, hB.z, a1); a2 = fmaf(w.w, hB.w, a2);
        }
        // reduce across the 8 k-chunk lanes
        #pragma unroll
        for (int m = 4; m > 0; m >>= 1) {
            a1 += __shfl_xor_sync(0xffffffffu, a1, m, 8);
            a2 += __shfl_xor_sync(0xffffffffu, a2, m, 8);
        }
        if (e == 0) {
            sg[0 * 32 + row] = a1 + pA;
            sg[1 * 32 + row] = a2 + pB;
        }
        __syncthreads();

        if (tid < 16) {
            int b = tid >> 3, u = tid & 7;
            float gi = sg[b * 32 + 0  + u];
            float gf = sg[b * 32 + 8  + u];
            float gg = sg[b * 32 + 16 + u];
            float go = sg[b * 32 + 24 + u];
            c_reg = sigm(gf) * c_reg + sigm(gi) * tanhf(gg);
            float hv = sigm(go) * tanhf(c_reg);
            ((float*)&g_hbuf[p ^ 1][u0 + u])[b] = hv;
            g_hseq[b][t][u0 + u] = hv;
            __threadfence();
        }
        grid_bar();
    }
}

// ---------------- final reduction: out = 5*exp(-sum|o1-o2|) ----------------
__global__ void final_k(float* __restrict__ out)
{
    __shared__ float red[256];
    int tid = threadIdx.x;
    float s = 0.f;
    for (int j = tid; j < HID; j += 256) {
        float a = g_hseq[0][T_SEQ - 1][j];
        float b = g_hseq[1][T_SEQ - 1][j];
        s += fabsf(a - b);
    }
    red[tid] = s;
    __syncthreads();
    for (int w = 128; w > 0; w >>= 1) {
        if (tid < w) red[tid] += red[tid + w];
        __syncthreads();
    }
    if (tid == 0) out[0] = 5.f * expf(-red[0]);
}

// ---------------- launch ----------------
extern "C" void kernel_launch(void* const* d_in, const int* in_sizes, int n_in,
                              void* d_out, int out_size)
{
    const float* s1   = (const float*)d_in[0];
    const float* s2   = (const float*)d_in[1];
    const float* h1_0 = (const float*)d_in[2];
    const float* c1_0 = (const float*)d_in[3];
    const float* h2_0 = (const float*)d_in[4];
    const float* c2_0 = (const float*)d_in[5];
    const float* W_ih = (const float*)d_in[6];  // [2][4096][1024]
    const float* W_hh = (const float*)d_in[7];  // [2][4096][1024]
    const float* b_ih = (const float*)d_in[8];  // [2][4096]
    const float* b_hh = (const float*)d_in[9];  // [2][4096]

    cudaFuncSetAttribute(lstm_rec, cudaFuncAttributeMaxDynamicSharedMemorySize, REC_SMEM);

    dim3 gg(G4 / BN, T_SEQ / BM, 2);

    // layer 0
    sgemm_nt_bias<<<gg, 256>>>(s1, s2, 0, W_ih, b_ih, b_hh);
    lstm_rec<<<REC_NC, 256, REC_SMEM>>>(W_hh, h1_0, h2_0, c1_0, c2_0);

    // layer 1 (input = layer-0 hidden sequence)
    const size_t woff = (size_t)G4 * KDIM;
    sgemm_nt_bias<<<gg, 256>>>(nullptr, nullptr, 1, W_ih + woff, b_ih + G4, b_hh + G4);
    lstm_rec<<<REC_NC, 256, REC_SMEM>>>(W_hh + woff, h1_0 + HID, h2_0 + HID,
                                        c1_0 + HID, c2_0 + HID);

    final_k<<<1, 256>>>((float*)d_out);
}